// round 4
// baseline (speedup 1.0000x reference)
#include <cuda_runtime.h>
#include <cstdint>

// high_order_input: x[4,8,128,128] f32 -> out[4,8,210,16384] f32
// ht2: 45 pairs col_i*col_j (i<=j); ht3: 165 triples col_i*col_j*col_k (i<=j<=k),
// enumeration order matches reference tpcm2/tpcm3 (verified: rel_err 3.9e-08).
// R4: persistent grid-stride, 1 px/thread, <=32 regs -> 2048 thr/SM, eliminating
// the 2-wave tail that left DRAM at 66% in R2. Kernel is HBM-write-bound.
// (R3 infra failure; also removed the static-cached SM count, which violated the
// harness's no-static-state contract. Attribute query now runs every call.)

#define HWDIM 128
#define LPIX  (HWDIM * HWDIM)   // 16384
#define NTERM 210
#define NPIX  (32 * LPIX)       // 524288 total pixels across 32 planes

__global__ __launch_bounds__(256, 8)
void high_order_kernel(const float* __restrict__ x, float* __restrict__ out)
{
    const int stride = gridDim.x * blockDim.x;
    for (int idx = blockIdx.x * blockDim.x + threadIdx.x; idx < NPIX; idx += stride) {
        const int plane = idx >> 14;          // idx / LPIX
        const int q     = idx & (LPIX - 1);
        const int h     = q >> 7;             // row
        const int w     = q & (HWDIM - 1);    // col

        const float* __restrict__ xp = x + (size_t)plane * LPIX;

        // 3x3 neighborhood with zero padding (row-major kh,kw order).
        float col[9];
        #pragma unroll
        for (int dr = 0; dr < 3; dr++) {
            const int r = h + dr - 1;
            const bool rok = (r >= 0) & (r < HWDIM);
            const float* rp = xp + r * HWDIM + w;
            col[dr * 3 + 0] = (rok && w > 0)         ? __ldg(rp - 1) : 0.f;
            col[dr * 3 + 1] = rok                    ? __ldg(rp)     : 0.f;
            col[dr * 3 + 2] = (rok && w < HWDIM - 1) ? __ldg(rp + 1) : 0.f;
        }

        float* __restrict__ obase = out + (size_t)plane * NTERM * LPIX + (size_t)q;

        // t2 = 0..44 (i-major, j>=i); t3 = 45..209 (i-major, j>=i, k>=j).
        // p is both the ht2 value and the shared prefix of all (i,j,*) triples.
        int t2 = 0;
        int t3 = 45;
        #pragma unroll
        for (int i = 0; i < 9; i++) {
            #pragma unroll
            for (int j = i; j < 9; j++) {
                const float p = col[i] * col[j];
                __stcs(obase + (size_t)t2 * LPIX, p);
                t2++;
                #pragma unroll
                for (int k = j; k < 9; k++) {
                    __stcs(obase + (size_t)t3 * LPIX, p * col[k]);
                    t3++;
                }
            }
        }
    }
}

extern "C" void kernel_launch(void* const* d_in, const int* in_sizes, int n_in,
                              void* d_out, int out_size)
{
    const float* x = (const float*)d_in[0];
    float* out = (float*)d_out;
    // tpcm2 (d_in[1]) / tpcm3 (d_in[2]) are compile-time constants for K=3; hardcoded.
    (void)in_sizes; (void)n_in; (void)out_size;

    // Persistent launch: 8 CTAs per SM (2048 threads = full occupancy at <=32
    // regs). Attribute query runs unconditionally every call — it is not a
    // stream operation (capture-safe), allocates nothing, and is deterministic.
    int num_sms = 0;
    cudaDeviceGetAttribute(&num_sms, cudaDevAttrMultiProcessorCount, 0);
    if (num_sms <= 0) num_sms = 148;
    const int block = 256;
    const int grid = num_sms * 8;
    high_order_kernel<<<grid, block>>>(x, out);
}

// round 5
// speedup vs baseline: 1.0082x; 1.0082x over previous
#include <cuda_runtime.h>
#include <cstdint>

// high_order_input: x[4,8,128,128] f32 -> out[4,8,210,16384] f32
// ht2: 45 pairs col_i*col_j (i<=j); ht3: 165 triples col_i*col_j*col_k (i<=j<=k),
// enumeration order matches reference tpcm2/tpcm3 (verified: rel_err 3.9e-08).
// R5: R2's winning shape (2 px/thread, STG.64 streaming stores) + 32-reg cap so
// all 1024 CTAs are resident in a single wave (8 CTAs/SM on 152 SMs = 1216 slots),
// removing R2's 112-CTA tail wave. Scalar-store (R4) and 4px (R1) variants both
// measured slower; STG.64 at full residency is the empirical sweet spot.

#define HWDIM 128
#define LPIX  (HWDIM * HWDIM)   // 16384
#define NTERM 210

__global__ __launch_bounds__(256, 8)
void high_order_kernel(const float* __restrict__ x, float* __restrict__ out)
{
    const int tid = blockIdx.x * blockDim.x + threadIdx.x;
    // 32 planes * 16384 pixels / 2 pixels-per-thread = 262144 threads
    const int plane = tid >> 13;          // tid / 8192
    const int q     = tid & 8191;
    const int h     = q >> 6;             // q / 64
    const int w0    = (q & 63) << 1;      // 2-pixel group start

    const float* __restrict__ xp = x + (size_t)plane * LPIX;

    // 3x3 neighborhood for 2 consecutive pixels: col[kh*3+kw] holds
    // x[h+kh-1][w0+kw-1 .. w0+kw] with zero padding.
    float2 col[9];
    #pragma unroll
    for (int dr = 0; dr < 3; dr++) {
        const int r = h + dr - 1;
        float v0, v3;
        float2 mid;
        if (r < 0 || r >= HWDIM) {
            v0 = 0.f; v3 = 0.f;
            mid = make_float2(0.f, 0.f);
        } else {
            const float* rp = xp + r * HWDIM + w0;
            mid = *reinterpret_cast<const float2*>(rp);          // aligned (w0 % 2 == 0)
            v0 = (w0 > 0)          ? __ldg(rp - 1) : 0.f;
            v3 = (w0 + 2 < HWDIM)  ? __ldg(rp + 2) : 0.f;
        }
        col[dr * 3 + 0] = make_float2(v0,    mid.x);
        col[dr * 3 + 1] = mid;
        col[dr * 3 + 2] = make_float2(mid.y, v3);
    }

    float* __restrict__ obase = out + (size_t)plane * NTERM * LPIX + (size_t)(h * HWDIM + w0);

    // t2 = 0..44 (i-major, j>=i); t3 = 45..209 (i-major, j>=i, k>=j).
    // p_ij is both the ht2 value and the shared prefix of all (i,j,*) triples.
    int t2 = 0;
    int t3 = 45;
    #pragma unroll
    for (int i = 0; i < 9; i++) {
        #pragma unroll
        for (int j = i; j < 9; j++) {
            float2 p;
            p.x = col[i].x * col[j].x;
            p.y = col[i].y * col[j].y;
            __stcs(reinterpret_cast<float2*>(obase + (size_t)t2 * LPIX), p);
            t2++;
            #pragma unroll
            for (int k = j; k < 9; k++) {
                float2 r;
                r.x = p.x * col[k].x;
                r.y = p.y * col[k].y;
                __stcs(reinterpret_cast<float2*>(obase + (size_t)t3 * LPIX), r);
                t3++;
            }
        }
    }
}

extern "C" void kernel_launch(void* const* d_in, const int* in_sizes, int n_in,
                              void* d_out, int out_size)
{
    const float* x = (const float*)d_in[0];
    float* out = (float*)d_out;
    // tpcm2 (d_in[1]) / tpcm3 (d_in[2]) are compile-time constants for K=3; hardcoded.
    (void)in_sizes; (void)n_in; (void)out_size;

    const int total_threads = 4 * 8 * (LPIX / 2);   // 262144
    const int block = 256;
    const int grid = total_threads / block;         // 1024 CTAs -> single wave @ 8/SM
    high_order_kernel<<<grid, block>>>(x, out);
}